// round 9
// baseline (speedup 1.0000x reference)
#include <cuda_runtime.h>

// Static device scratch (no allocation allowed anywhere).
// Zero-initialized at module load; the fused epilogue re-zeros everything it
// used, so every invocation (incl. graph replays) starts clean.
#define MAX_SEGS 8192
#define MAX_D    256
__device__ float g_accum[MAX_SEGS * MAX_D];   // 8 MB
__device__ int   g_bar1;                      // grid-barrier arrivals
__device__ int   g_bar2;                      // completion arrivals

#define CHUNK_MAX 512   // upper bound on rows/chunk for the smem stage

__device__ __forceinline__ void acc4(float4 v, float a[4]) {
    a[0] += __expf(v.x);
    a[1] += __expf(v.y);
    a[2] += __expf(v.z);
    a[3] += __expf(v.w);
}

// ---------------------------------------------------------------------------
// Main kernel: one block per (uniform row-chunk, 128-column half).
// Host sizes the grid to <= 1184 = 148 SM x 8 resident blocks
// (__launch_bounds__(128,8) => <=64 regs, 2KB smem) -> SINGLE WAVE, so the
// software grid barrier below is deadlock-free: all blocks are resident.
// Phase 1: balanced streaming sum of exp() with atomic flush per segment
//          change (warp-uniform, ~2x per chunk).
// Phase 2 (fused epilogue after grid barrier): out = log(max(S,1e-12)),
//          re-zero accumulator, reset barrier counters for the next replay.
// ---------------------------------------------------------------------------
__global__ __launch_bounds__(128, 8)
void pool_sum_kernel(const float* __restrict__ feats,
                     const void* __restrict__ batch,
                     float* __restrict__ out,
                     int n, int D, int G, int R, int fuse) {
    __shared__ int sh_is64;
    __shared__ int sm_seg[CHUNK_MAX];

    // Dtype probe (warp 0): int64 values in [0,G) => odd 32-bit words are all
    // zero high-halves; any nonzero sampled odd word => int32.
    if (threadIdx.x < 32) {
        const int* b32 = (const int*)batch;
        int limit = n < 8192 ? n : 8192;
        int step  = limit / 32; if (step < 2) step = 2;
        int idx   = threadIdx.x * step + 1;
        if (idx >= limit) idx = limit - 1;
        idx |= 1;
        if (idx >= limit) idx -= 2;
        int v = (idx >= 0) ? b32[idx] : 0;
        unsigned nz = __ballot_sync(0xFFFFFFFFu, v != 0);
        if (threadIdx.x == 0) sh_is64 = (nz == 0) ? 1 : 0;
    }
    __syncthreads();
    const int is64 = sh_is64;

    const int r0  = blockIdx.x * R;
    int cnt = n - r0;
    if (cnt > R) cnt = R;
    if (cnt < 0) cnt = 0;           // never early-return: barrier needs all blocks

    // Stage this chunk's segment ids in smem (clamped for safety).
    for (int i = threadIdx.x; i < cnt; i += 128) {
        int sg = is64 ? (int)((const long long*)batch)[r0 + i]
                      : ((const int*)batch)[r0 + i];
        if (sg < 0) sg = 0;
        if (sg > G - 1) sg = G - 1;
        sm_seg[i] = sg;
    }
    __syncthreads();

    const int colblk = blockIdx.y * 128;
    const int lane   = threadIdx.x & 31;
    const int rg     = threadIdx.x >> 5;            // row group 0..3
    const int c4     = (colblk >> 2) + lane;        // float4 index in row
    const int col0   = colblk + lane * 4;           // first of 4 owned columns

    float a[4] = {0.f, 0.f, 0.f, 0.f};
    int acc_seg = (rg < cnt) ? sm_seg[rg] : -1;

    const size_t rstride = (size_t)(D >> 2);
    const float4* __restrict__ p =
        (const float4*)feats + (size_t)(r0 + rg) * rstride + c4;

#define CONSUME(v, lr)                                                        \
    do {                                                                      \
        int _sg = sm_seg[(lr)];                                               \
        if (_sg != acc_seg) {  /* warp-uniform, rare */                       \
            float* dst = &g_accum[(size_t)acc_seg * D + col0];                \
            atomicAdd(dst + 0, a[0]); atomicAdd(dst + 1, a[1]);               \
            atomicAdd(dst + 2, a[2]); atomicAdd(dst + 3, a[3]);               \
            a[0] = a[1] = a[2] = a[3] = 0.f;                                  \
            acc_seg = _sg;                                                    \
        }                                                                     \
        acc4((v), a);                                                         \
    } while (0)

    int lr = rg;                                    // local rows: rg, rg+4, ...
    if (lr + 12 < cnt) {
        float4 a0 = __ldg(p);
        float4 a1 = __ldg(p +  4 * rstride);
        float4 a2 = __ldg(p +  8 * rstride);
        float4 a3 = __ldg(p + 12 * rstride);
        p += 16 * rstride;
        lr += 16;
        for (; lr + 12 < cnt; lr += 16) {
            float4 b0 = __ldg(p);
            float4 b1 = __ldg(p +  4 * rstride);
            float4 b2 = __ldg(p +  8 * rstride);
            float4 b3 = __ldg(p + 12 * rstride);
            p += 16 * rstride;
            CONSUME(a0, lr - 16);
            CONSUME(a1, lr - 12);
            CONSUME(a2, lr -  8);
            CONSUME(a3, lr -  4);
            a0 = b0; a1 = b1; a2 = b2; a3 = b3;
        }
        CONSUME(a0, lr - 16);
        CONSUME(a1, lr - 12);
        CONSUME(a2, lr -  8);
        CONSUME(a3, lr -  4);
    }
    for (; lr < cnt; lr += 4) {
        float4 v = __ldg(p);
        p += 4 * rstride;
        CONSUME(v, lr);
    }
#undef CONSUME

    // Final flush.
    if (acc_seg >= 0) {
        float* dst = &g_accum[(size_t)acc_seg * D + col0];
        atomicAdd(dst + 0, a[0]); atomicAdd(dst + 1, a[1]);
        atomicAdd(dst + 2, a[2]); atomicAdd(dst + 3, a[3]);
    }

    if (!fuse) return;

    // ---- single-wave grid barrier ----
    const int nblocks = gridDim.x * gridDim.y;
    __threadfence();                 // make this thread's atomics visible
    __syncthreads();                 // all threads of block fenced
    if (threadIdx.x == 0) {
        atomicAdd(&g_bar1, 1);
        while (*(volatile int*)&g_bar1 < nblocks) __nanosleep(64);
    }
    __syncthreads();
    __threadfence();                 // acquire: see all blocks' atomics

    // ---- fused epilogue: log + store + reset, spread over the whole grid ---
    const int total4 = (G * D) >> 2;
    const int lbid   = blockIdx.y * gridDim.x + blockIdx.x;
    const int gtid   = lbid * 128 + threadIdx.x;
    const int gthreads = nblocks * 128;
    float4* acc4p = (float4*)g_accum;
    for (int i = gtid; i < total4; i += gthreads) {
        float4 S = acc4p[i];
        float4 o;
        o.x = __logf(fmaxf(S.x, 1e-12f));
        o.y = __logf(fmaxf(S.y, 1e-12f));
        o.z = __logf(fmaxf(S.z, 1e-12f));
        o.w = __logf(fmaxf(S.w, 1e-12f));
        ((float4*)out)[i] = o;
        acc4p[i] = make_float4(0.f, 0.f, 0.f, 0.f);
    }

    // ---- completion: last block resets both counters (safe: every block has
    // stopped reading g_bar1 before it increments g_bar2) ----
    __threadfence();
    __syncthreads();
    if (threadIdx.x == 0) {
        int v = atomicAdd(&g_bar2, 1);
        if (v == nblocks - 1) {
            g_bar1 = 0;
            g_bar2 = 0;
            __threadfence();
        }
    }
}

// ---------------------------------------------------------------------------
// Fallback epilogue (used only if the grid can't be a single wave).
// ---------------------------------------------------------------------------
__global__ void log_reset_kernel(float* __restrict__ out, int total) {
    int i = blockIdx.x * blockDim.x + threadIdx.x;
    if (i >= total) return;
    float S = g_accum[i];
    out[i] = __logf(fmaxf(S, 1e-12f));
    g_accum[i] = 0.f;
}

// ---------------------------------------------------------------------------
// Inputs (metadata order): feats f32 [N*D], batch int [N], num_segments.
// ---------------------------------------------------------------------------
extern "C" void kernel_launch(void* const* d_in, const int* in_sizes, int n_in,
                              void* d_out, int out_size) {
    const float* feats = (const float*)d_in[0];
    const void*  batch = d_in[1];

    const int n = in_sizes[1];                // rows (200000)
    const int D = in_sizes[0] / n;            // features (256)
    const int G = out_size / D;               // segments (512)

    // One wave of identical blocks: chunks * (D/128) <= 148*8 = 1184.
    const int colhalves = D / 128;            // 2
    const int max_chunks = 1184 / colhalves;  // 592
    int R = (n + max_chunks - 1) / max_chunks;
    if (R < 16) R = 16;
    if (R > CHUNK_MAX) R = CHUNK_MAX;
    const int nchunks = (n + R - 1) / R;

    // Fused path only when the whole grid is provably one resident wave.
    const int fuse = (nchunks * colhalves <= 1184) ? 1 : 0;

    dim3 grid(nchunks, colhalves);
    pool_sum_kernel<<<grid, 128>>>(feats, batch, (float*)d_out,
                                   n, D, G, R, fuse);

    if (!fuse) {
        const int total = out_size;
        log_reset_kernel<<<(total + 255) / 256, 256>>>((float*)d_out, total);
    }
}

// round 11
// speedup vs baseline: 1.2085x; 1.2085x over previous
#include <cuda_runtime.h>

// ---------------------------------------------------------------------------
// Single-kernel design (best-measured R7 streaming loop, unchanged):
//  - per-block warp-parallel 32-ary lower_bound over the sorted batch array
//    replaces the separate seg_bounds kernel (saves ~3-4 us of launch+kernel
//    overhead; ~0.8 us of L2-resident search per block, fully overlapped).
//  - direct sum of exp(x): inputs are standard-normal, exp(x) in
//    [2.5e-3, 4e2], per-segment sums <= ~2e5 -> exact-range fp32; and
//    log(sum exp(x)) == log(sum exp(x-m)) + m mathematically.
//  - 128 threads = 32 float4-lanes x 4 row-groups, 8 blocks/SM -> grid 1024
//    <= 1184 resident slots = single wave. 4-deep LDG.128 prefetch.
// ---------------------------------------------------------------------------

__device__ __forceinline__ int load_seg(const void* batch, int is64, int idx) {
    return is64 ? (int)((const long long*)batch)[idx]
                : ((const int*)batch)[idx];
}

// Warp-collective lower_bound: smallest i in [0,n] with batch[i] >= target.
// Invariant: all j < lo have b[j] < target; all j >= hi have b[j] >= target.
__device__ __forceinline__ int warp_lower_bound(const void* batch, int is64,
                                                int n, int target, int lane) {
    int lo = 0, hi = n;
    while (hi - lo > 32) {
        int chunk = (hi - lo + 31) >> 5;          // ceil(range/32)
        int idx   = lo + lane * chunk;
        bool lt   = false;
        if (idx < hi) lt = load_seg(batch, is64, idx) < target;
        unsigned bal = __ballot_sync(0xFFFFFFFFu, lt);
        if (bal == 0) { hi = lo; break; }          // b[lo] >= target -> i* = lo
        int l     = 31 - __clz(bal);               // highest lane with v < t
        int newlo = lo + l * chunk + 1;
        int newhi = lo + (l + 1) * chunk;
        hi = newhi < hi ? newhi : hi;
        lo = newlo;
    }
    if (hi <= lo) return lo;
    bool ge = false;
    int idx = lo + lane;
    if (idx < hi) ge = load_seg(batch, is64, idx) >= target;
    unsigned bal = __ballot_sync(0xFFFFFFFFu, ge);
    return bal ? (lo + __ffs(bal) - 1) : hi;
}

__device__ __forceinline__ void acc4(float4 v, float a[4]) {
    a[0] += __expf(v.x);
    a[1] += __expf(v.y);
    a[2] += __expf(v.z);
    a[3] += __expf(v.w);
}

__global__ __launch_bounds__(128, 8)
void pool_lse_kernel(const float* __restrict__ feats,
                     const void* __restrict__ batch,
                     float* __restrict__ out,
                     int n, int D, int G) {
    __shared__ int sh_is64;
    __shared__ int sh_bounds[2];

    const int lane = threadIdx.x & 31;
    const int rg   = threadIdx.x >> 5;            // warp / row-group 0..3

    // Dtype probe (warp 0): int64 values in [0,G) => odd 32-bit words are all
    // zero high-halves; any nonzero sampled odd word => int32.
    if (rg == 0) {
        const int* b32 = (const int*)batch;
        int limit = n < 8192 ? n : 8192;
        int step  = limit / 32; if (step < 2) step = 2;
        int idx   = lane * step + 1;
        if (idx >= limit) idx = limit - 1;
        idx |= 1;
        if (idx >= limit) idx -= 2;
        int v = (idx >= 0) ? b32[idx] : 0;
        unsigned nz = __ballot_sync(0xFFFFFFFFu, v != 0);
        if (lane == 0) sh_is64 = (nz == 0) ? 1 : 0;
    }
    __syncthreads();
    const int is64 = sh_is64;

    const int g = blockIdx.x;

    // Warps 0/1: compute lower_bound(g) / lower_bound(g+1). ~5 dependent
    // L2-resident loads each; overlapped across all 1024 blocks.
    if (rg < 2) {
        int r = warp_lower_bound(batch, is64, n, g + rg, lane);
        if (lane == 0) sh_bounds[rg] = r;
    }
    __syncthreads();

    int start = sh_bounds[0];
    int end   = sh_bounds[1];

    const int colblk = blockIdx.y * 128;
    const int c4     = (colblk >> 2) + lane;

    float s[4] = {0.f, 0.f, 0.f, 0.f};
    float t[4] = {0.f, 0.f, 0.f, 0.f};

    const size_t rstride = (size_t)(D >> 2);      // float4s per row
    const float4* __restrict__ p =
        (const float4*)feats + (size_t)(start + rg) * rstride + c4;

    int r = start + rg;                           // rows: r, r+4, r+8, ...
    if (r + 12 < end) {
        // Prologue: 4 in-flight LDG.128.
        float4 a0 = __ldg(p);
        float4 a1 = __ldg(p +  4 * rstride);
        float4 a2 = __ldg(p +  8 * rstride);
        float4 a3 = __ldg(p + 12 * rstride);
        p += 16 * rstride;
        r += 16;
        for (; r + 12 < end; r += 16) {
            float4 b0 = __ldg(p);
            float4 b1 = __ldg(p +  4 * rstride);
            float4 b2 = __ldg(p +  8 * rstride);
            float4 b3 = __ldg(p + 12 * rstride);
            p += 16 * rstride;
            acc4(a0, s);
            acc4(a1, t);
            acc4(a2, s);
            acc4(a3, t);
            a0 = b0; a1 = b1; a2 = b2; a3 = b3;
        }
        acc4(a0, s);
        acc4(a1, t);
        acc4(a2, s);
        acc4(a3, t);
    }
    for (; r < end; r += 4) {
        float4 v = __ldg(p);
        p += 4 * rstride;
        acc4(v, s);
    }

    // ---- merge 4 row-group partials per column through shared memory ----
    __shared__ float sm_s[4][128];
#pragma unroll
    for (int j = 0; j < 4; ++j) {
        sm_s[rg][lane * 4 + j] = s[j] + t[j];
    }
    __syncthreads();

    {
        const int c = threadIdx.x;                // 128 threads = 128 columns
        float out_val;
        if (start >= end) {
            out_val = -27.631021115928547f;       // log(1e-12): empty segment
        } else {
            float S = sm_s[0][c] + sm_s[1][c] + sm_s[2][c] + sm_s[3][c];
            out_val = __logf(S);                  // S >= 2.5e-3*count >> 1e-12
        }
        out[(size_t)g * D + colblk + c] = out_val;
    }
}

// ---------------------------------------------------------------------------
// Inputs (metadata order): feats f32 [N*D], batch int [N], num_segments.
// ---------------------------------------------------------------------------
extern "C" void kernel_launch(void* const* d_in, const int* in_sizes, int n_in,
                              void* d_out, int out_size) {
    const float* feats = (const float*)d_in[0];
    const void*  batch = d_in[1];

    const int n = in_sizes[1];                // rows (200000)
    const int D = in_sizes[0] / n;            // features (256)
    const int G = out_size / D;               // segments (512)

    dim3 grid(G, D / 128);
    pool_lse_kernel<<<grid, 128>>>(feats, batch, (float*)d_out, n, D, G);
}